// round 1
// baseline (speedup 1.0000x reference)
#include <cuda_runtime.h>

#define SEQ   600
#define TOUT  594   // SEQ - P
#define PP    6
#define KD    7
#define NW    8     // warps (rows) per block
#define ROWPAD (SEQ + 8)

__global__ __launch_bounds__(NW * 32)
void ar_kernel(const float* __restrict__ x, float* __restrict__ out, int N) {
    __shared__ float sh[NW][ROWPAD];

    const int warp = threadIdx.x >> 5;
    const int lane = threadIdx.x & 31;
    const int row  = blockIdx.x * NW + warp;
    if (row >= N) return;

    // ---- Load row (600 floats = 150 float4) into shared, coalesced ----
    const float4* xv = (const float4*)(x + (size_t)row * SEQ);
    float4* sv = (float4*)sh[warp];
    #pragma unroll
    for (int i = 0; i < 5; i++) {
        int j = lane + i * 32;
        if (j < 150) sv[j] = xv[j];
    }
    __syncwarp();
    const float* s = sh[warp];

    // ---- Accumulate normal equations: G (28 upper-tri) and b (7) ----
    float G[28], bb[KD];
    #pragma unroll
    for (int i = 0; i < 28; i++) G[i] = 0.f;
    #pragma unroll
    for (int i = 0; i < KD; i++) bb[i] = 0.f;

    for (int t = lane; t < TOUT; t += 32) {
        float d[KD];
        d[0] = 1.f;
        d[1] = s[t + 5];
        d[2] = s[t + 4];
        d[3] = s[t + 3];
        d[4] = s[t + 2];
        d[5] = s[t + 1];
        d[6] = s[t + 0];
        const float y = s[t + 6];
        int idx = 0;
        #pragma unroll
        for (int k = 0; k < KD; k++) {
            #pragma unroll
            for (int l = k; l < KD; l++) {
                G[idx] = fmaf(d[k], d[l], G[idx]);
                idx++;
            }
            bb[k] = fmaf(d[k], y, bb[k]);
        }
    }

    // ---- Warp butterfly reduction ----
    #pragma unroll
    for (int i = 0; i < 28; i++) {
        #pragma unroll
        for (int o = 16; o > 0; o >>= 1)
            G[i] += __shfl_xor_sync(0xffffffffu, G[i], o);
    }
    #pragma unroll
    for (int i = 0; i < KD; i++) {
        #pragma unroll
        for (int o = 16; o > 0; o >>= 1)
            bb[i] += __shfl_xor_sync(0xffffffffu, bb[i], o);
    }

    // ---- Lane 0: fp64 Cholesky solve of SPD 7x7 (fully unrolled -> regs) ----
    float wf[KD];
    if (lane == 0) {
        double A[KD][KD];
        {
            int idx = 0;
            #pragma unroll
            for (int k = 0; k < KD; k++)
                #pragma unroll
                for (int l = k; l < KD; l++) {
                    double v = (double)G[idx]; idx++;
                    A[k][l] = v; A[l][k] = v;
                }
        }
        double bd[KD];
        #pragma unroll
        for (int k = 0; k < KD; k++) bd[k] = (double)bb[k];

        // Cholesky: A(lower) <- L
        #pragma unroll
        for (int c = 0; c < KD; c++) {
            double sd = A[c][c];
            #pragma unroll
            for (int k = 0; k < c; k++) sd -= A[c][k] * A[c][k];
            double lcc = sqrt(sd);
            A[c][c] = lcc;
            double inv = 1.0 / lcc;
            #pragma unroll
            for (int r = c + 1; r < KD; r++) {
                double s2 = A[r][c];
                #pragma unroll
                for (int k = 0; k < c; k++) s2 -= A[r][k] * A[c][k];
                A[r][c] = s2 * inv;
            }
        }
        // Forward solve L z = b
        double z[KD];
        #pragma unroll
        for (int r = 0; r < KD; r++) {
            double s2 = bd[r];
            #pragma unroll
            for (int k = 0; k < r; k++) s2 -= A[r][k] * z[k];
            z[r] = s2 / A[r][r];
        }
        // Back solve L^T w = z
        double wd[KD];
        #pragma unroll
        for (int c = KD - 1; c >= 0; c--) {
            double s2 = z[c];
            #pragma unroll
            for (int k = c + 1; k < KD; k++) s2 -= A[k][c] * wd[k];
            wd[c] = s2 / A[c][c];
        }
        #pragma unroll
        for (int j = 0; j < KD; j++) wf[j] = (float)wd[j];
    }
    #pragma unroll
    for (int j = 0; j < KD; j++)
        wf[j] = __shfl_sync(0xffffffffu, wf[j], 0);

    // ---- Output layout (flat, reference tuple order) ----
    // coeffs  : [0,              N*3600)
    // p_logits: [N*3600,         N*3605)
    // p_hard  : [N*3605,         N*3606)  (int32 zeros == float 0.0 bits)
    // x_hat   : [N*3606,         N*4206)
    const size_t Ns = (size_t)N;
    float* coeffs = out;
    float* plog   = out + Ns * 3600;
    int*   phard  = (int*)(out + Ns * 3605);
    float* xhat   = out + Ns * 3606;

    // ---- coeffs: repeating [w1..w6] pattern, float4 stores (period lcm=12) ----
    const float4 p0 = make_float4(wf[1], wf[2], wf[3], wf[4]);
    const float4 p1 = make_float4(wf[5], wf[6], wf[1], wf[2]);
    const float4 p2 = make_float4(wf[3], wf[4], wf[5], wf[6]);
    const float4 z4 = make_float4(0.f, 0.f, 0.f, 0.f);
    float4* cv = (float4*)(coeffs + (size_t)row * 3600);
    for (int j = lane; j < 900; j += 32) {
        float4 v;
        if (j < 9) {            // t < 6 -> masked to zero (36 floats = 9 float4)
            v = z4;
        } else {
            int m = j - (j / 3) * 3;
            v = (m == 0) ? p0 : ((m == 1) ? p1 : p2);
        }
        cv[j] = v;
    }

    // ---- p_logits / p_hard: zeros ----
    if (lane < 5) plog[(size_t)row * 5 + lane] = 0.f;
    if (lane == 5) phard[row] = 0;

    // ---- x_hat: 0 for t<6, else w0 + sum w[k]*x[t-k] ----
    float* xr = xhat + (size_t)row * SEQ;
    for (int t = lane; t < SEQ; t += 32) {
        float v = 0.f;
        if (t >= PP) {
            v = wf[0];
            v = fmaf(wf[1], s[t - 1], v);
            v = fmaf(wf[2], s[t - 2], v);
            v = fmaf(wf[3], s[t - 3], v);
            v = fmaf(wf[4], s[t - 4], v);
            v = fmaf(wf[5], s[t - 5], v);
            v = fmaf(wf[6], s[t - 6], v);
        }
        xr[t] = v;
    }
}

extern "C" void kernel_launch(void* const* d_in, const int* in_sizes, int n_in,
                              void* d_out, int out_size) {
    const float* x = (const float*)d_in[0];
    const int N = in_sizes[0] / SEQ;
    float* out = (float*)d_out;
    const int blocks = (N + NW - 1) / NW;
    ar_kernel<<<blocks, NW * 32>>>(x, out, N);
}